// round 9
// baseline (speedup 1.0000x reference)
#include <cuda_runtime.h>
#include <cuda_fp16.h>
#include <cstdint>

// Problem constants
#define Bsz 4096
#define Vn  50
#define Fn  15
#define Hn  256
#define Gn  1024   // 4*H

// ---------------- scratch (static device globals; no allocation) ----------
__device__ float g_c1 [Bsz * Hn];
__device__ float g_c2 [Bsz * Hn];
__device__ float g_h1f[Bsz * Hn];
__device__ float g_h2f[Bsz * Hn];
// ping-pong fp16-split hidden states (race-free across a scan step)
__device__ __half g_h1hi[2][Bsz * Hn];
__device__ __half g_h1lo[2][Bsz * Hn];
__device__ __half g_h2hi[2][Bsz * Hn];
__device__ __half g_h2lo[2][Bsz * Hn];
// fp16-split, gate-remapped weights  [n'][256] with n' = 4u+gate interleave
__device__ __half g_w1hi[Gn * Hn], g_w1lo[Gn * Hn];
__device__ __half g_w2hi[Gn * Hn], g_w2lo[Gn * Hn];
__device__ __half g_wx1hi[Gn * 16], g_wx1lo[Gn * 16];
__device__ __half g_wx2hi[Gn * 16], g_wx2lo[Gn * 16];
// fp16-split per-step inputs xs[v][b][16] (col 15 zero)
__device__ __half g_xshi[Vn * Bsz * 16], g_xslo[Vn * Bsz * 16];
__device__ float g_badd1[Gn];           // lstm1 bih+bhh, remapped order
__device__ float g_m1[Bsz * 1024];
__device__ float g_m2[Bsz * 1024];
__device__ float g_m3[Bsz * 512];
__device__ float g_m4[Bsz * 256];
__device__ float g_pre2[Bsz * Gn];

typedef unsigned long long ull;

__device__ __forceinline__ void dup2(ull& d, float s) {
    asm("mov.b64 %0,{%1,%1};" : "=l"(d) : "f"(s));
}
__device__ __forceinline__ void ffma2(ull& d, ull a, ull b) {
    asm("fma.rn.f32x2 %0,%1,%2,%0;" : "+l"(d) : "l"(a), "l"(b));
}
__device__ __forceinline__ float2 u2f(ull u) {
    float2 f; asm("mov.b64 {%0,%1},%2;" : "=f"(f.x), "=f"(f.y) : "l"(u)); return f;
}
__device__ __forceinline__ float fsig(float x)  { return 1.0f / (1.0f + expf(-x)); }

// ---------------- warp-MMA helpers (sm_80+ baseline; runs as HMMA) ----------
__device__ __forceinline__ uint32_t smem_u32(const void* p) {
    uint32_t a;
    asm("{ .reg .u64 t; cvta.to.shared.u64 t, %1; cvt.u32.u64 %0, t; }" : "=r"(a) : "l"(p));
    return a;
}
__device__ __forceinline__ void ldm_x4(uint32_t* r, uint32_t addr) {
    asm volatile("ldmatrix.sync.aligned.m8n8.x4.shared.b16 {%0,%1,%2,%3}, [%4];"
        : "=r"(r[0]), "=r"(r[1]), "=r"(r[2]), "=r"(r[3]) : "r"(addr));
}
__device__ __forceinline__ void ldm_x2(uint32_t* r, uint32_t addr) {
    asm volatile("ldmatrix.sync.aligned.m8n8.x2.shared.b16 {%0,%1}, [%2];"
        : "=r"(r[0]), "=r"(r[1]) : "r"(addr));
}
__device__ __forceinline__ void mma16816(float* d, const uint32_t* a, const uint32_t* b) {
    asm volatile("mma.sync.aligned.m16n8k16.row.col.f32.f16.f16.f32 "
        "{%0,%1,%2,%3},{%4,%5,%6,%7},{%8,%9},{%0,%1,%2,%3};"
        : "+f"(d[0]), "+f"(d[1]), "+f"(d[2]), "+f"(d[3])
        : "r"(a[0]), "r"(a[1]), "r"(a[2]), "r"(a[3]), "r"(b[0]), "r"(b[1]));
}

// smem row stride (halves): 16 data + 8 pad = 48 bytes/row.
// 16B-aligned for uint4/ldmatrix (48 % 16 == 0); conflict-free: row start
// banks 12r mod 32 for r=0..7 = {0,12,24,4,16,28,8,20} -> 4-bank spans tile
// all 32 banks exactly. (LDP=20 faulted: 40B rows are only 8B-aligned.)
#define LDP 24

// ---------------- fused LSTM step (fp16-split MMA, double-buffered) ---------
// gates[m, n'] (n' = remapped 4u+gate) = h @ Whh'^T + x @ Wx'^T via 3 passes
// (hi*hi + hi*lo + lo*hi) of m16n8k16 f16 MMA, fp32 accumulate.
// Pipeline: prefetch chunk c+1 from gmem into regs while MMA-ing chunk c;
// double-buffered smem, ONE __syncthreads per chunk.
template <int USE_PRE2>
__global__ void __launch_bounds__(256, 2) lstm_step_mma(
    const __half* __restrict__ hA_hi, const __half* __restrict__ hA_lo,
    const __half* __restrict__ W_hi,  const __half* __restrict__ W_lo,
    const __half* __restrict__ Wx_hi, const __half* __restrict__ Wx_lo,
    const __half* __restrict__ xs_hi, const __half* __restrict__ xs_lo,
    const float* __restrict__ preact,
    float* __restrict__ cSt, float* __restrict__ hF,
    __half* __restrict__ hO_hi, __half* __restrict__ hO_lo)
{
    __shared__ __align__(16) __half shA[2][2][128 * LDP];   // [buf][hi/lo]
    __shared__ __align__(16) __half shW[2][2][128 * LDP];

    const int tid  = threadIdx.x;
    const int wid  = tid >> 5;
    const int lane = tid & 31;
    const int n0 = blockIdx.x * 128;   // remapped gate-col base
    const int m0 = blockIdx.y * 128;   // batch-row base
    const int wm0 = (wid & 1) * 64;    // warp m offset
    const int wn0 = (wid >> 1) * 32;   // warp n offset

    float acc[4][4][4];
#pragma unroll
    for (int i = 0; i < 4; i++)
#pragma unroll
        for (int j = 0; j < 4; j++)
#pragma unroll
            for (int k = 0; k < 4; k++) acc[i][j][k] = 0.f;

    // staging indices: 256 threads cover 128 rows x 2 8-half blocks
    const int row = tid >> 1;
    const int blk = tid & 1;
    const uint32_t stoff = (uint32_t)(row * LDP + blk * 8) * 2;   // 16B aligned

    // ldmatrix lane addressing
    const int l15 = lane & 15;
    const uint32_t aoff = ((uint32_t)((wm0 + l15) * LDP + (lane >> 4) * 8)) * 2;
    const int bl = lane & 7;
    const uint32_t boffbase = ((uint32_t)((wn0 + bl) * LDP + ((lane >> 3) & 1) * 8)) * 2;

    // gmem row bases (constant across chunks)
    const __half* pAh = hA_hi + (size_t)(m0 + row) * Hn + blk * 8;
    const __half* pAl = hA_lo + (size_t)(m0 + row) * Hn + blk * 8;
    const __half* pWh = W_hi + (size_t)(n0 + row) * Hn + blk * 8;
    const __half* pWl = W_lo + (size_t)(n0 + row) * Hn + blk * 8;
    const __half* pXh = xs_hi + (size_t)(m0 + row) * 16 + blk * 8;
    const __half* pXl = xs_lo + (size_t)(m0 + row) * 16 + blk * 8;
    const __half* pVh = Wx_hi + (size_t)(n0 + row) * 16 + blk * 8;
    const __half* pVl = Wx_lo + (size_t)(n0 + row) * 16 + blk * 8;

    uint4 vah, val, vwh, vwl;
    // ---- preload chunk 0 ----
    vah = *(const uint4*)pAh;      val = *(const uint4*)pAl;
    vwh = *(const uint4*)pWh;      vwl = *(const uint4*)pWl;
    *(uint4*)((char*)&shA[0][0][0] + stoff) = vah;
    *(uint4*)((char*)&shA[0][1][0] + stoff) = val;
    *(uint4*)((char*)&shW[0][0][0] + stoff) = vwh;
    *(uint4*)((char*)&shW[0][1][0] + stoff) = vwl;
    __syncthreads();

    for (int c = 0; c < 17; c++) {
        // ---- prefetch chunk c+1 into registers ----
        if (c < 16) {
            if (c + 1 < 16) {
                vah = *(const uint4*)(pAh + (c + 1) * 16);
                val = *(const uint4*)(pAl + (c + 1) * 16);
                vwh = *(const uint4*)(pWh + (c + 1) * 16);
                vwl = *(const uint4*)(pWl + (c + 1) * 16);
            } else {
                vah = *(const uint4*)pXh;  val = *(const uint4*)pXl;
                vwh = *(const uint4*)pVh;  vwl = *(const uint4*)pVl;
            }
        }

        const int cb = c & 1;
        const uint32_t sA0 = smem_u32(&shA[cb][0][0]);
        const uint32_t sA1 = smem_u32(&shA[cb][1][0]);
        const uint32_t sW0 = smem_u32(&shW[cb][0][0]);
        const uint32_t sW1 = smem_u32(&shW[cb][1][0]);

        // ---- B fragments for this k16 (4 n-frags, hi+lo) ----
        uint32_t bh[4][2], blo[4][2];
#pragma unroll
        for (int nf = 0; nf < 4; nf++) {
            uint32_t bo = boffbase + (uint32_t)(nf * 8 * LDP) * 2;
            ldm_x2(bh[nf], sW0 + bo);
            ldm_x2(blo[nf], sW1 + bo);
        }
        // ---- A fragments per m-tile, 3-pass MMA ----
#pragma unroll
        for (int mt = 0; mt < 4; mt++) {
            uint32_t ao = aoff + (uint32_t)(mt * 16 * LDP) * 2;
            uint32_t ah[4], al[4];
            ldm_x4(ah, sA0 + ao);
            ldm_x4(al, sA1 + ao);
#pragma unroll
            for (int nf = 0; nf < 4; nf++) {
                mma16816(acc[mt][nf], ah, bh[nf]);
                mma16816(acc[mt][nf], ah, blo[nf]);
                mma16816(acc[mt][nf], al, bh[nf]);
            }
        }

        // ---- store prefetched chunk into the other buffer ----
        if (c < 16) {
            const int nb = cb ^ 1;
            *(uint4*)((char*)&shA[nb][0][0] + stoff) = vah;
            *(uint4*)((char*)&shA[nb][1][0] + stoff) = val;
            *(uint4*)((char*)&shW[nb][0][0] + stoff) = vwh;
            *(uint4*)((char*)&shW[nb][1][0] + stoff) = vwl;
            __syncthreads();
        }
    }

    // ---- epilogue: combine gate pairs via shfl, LSTM cell update ----
    const bool odd = (lane & 1);
#pragma unroll
    for (int mt = 0; mt < 4; mt++) {
#pragma unroll
        for (int nf = 0; nf < 4; nf++) {
            float c0 = acc[mt][nf][0], c1 = acc[mt][nf][1];
            float c2 = acc[mt][nf][2], c3 = acc[mt][nf][3];
            // even lanes hold (i,f) of rows r,r+8; odd lanes hold (g,o)
            float v0 = odd ? c0 : c2;
            float v1 = odd ? c1 : c3;
            float r0 = __shfl_xor_sync(0xffffffffu, v0, 1);
            float r1 = __shfl_xor_sync(0xffffffffu, v1, 1);
            float gi = odd ? r0 : c0;
            float gf = odd ? r1 : c1;
            float gg = odd ? c2 : r0;
            float go = odd ? c3 : r1;
            int m = m0 + wm0 + mt * 16 + (lane >> 2) + (odd ? 8 : 0);
            int nb = n0 + wn0 + nf * 8 + ((lane >> 1) & 1) * 4;   // = 4*u
            float4 p = USE_PRE2 ? *(const float4*)(preact + (size_t)m * Gn + nb)
                                : *(const float4*)(preact + nb);
            gi += p.x; gf += p.y; gg += p.z; go += p.w;
            int u = nb >> 2;
            size_t ci = (size_t)m * Hn + u;
            float cold = cSt[ci];
            float iv = fsig(gi), fv = fsig(gf);
            float gv = tanhf(gg), ov = fsig(go);
            float cn = fv * cold + iv * gv;
            cSt[ci] = cn;
            float h = ov * tanhf(cn);
            hF[ci] = h;
            __half hh = __float2half_rn(h);
            hO_hi[ci] = hh;
            hO_lo[ci] = __float2half_rn(h - __half2float(hh));
        }
    }
}

// ---------------- prep kernels ----------------------------------------------
__global__ void zero_states_kernel() {
    int idx = blockIdx.x * blockDim.x + threadIdx.x;
    if (idx < Bsz * Hn) {
        g_c1[idx] = 0.f; g_c2[idx] = 0.f;
        __half z = __float2half_rn(0.f);
        g_h1hi[0][idx] = z; g_h1lo[0][idx] = z;
        g_h2hi[0][idx] = z; g_h2lo[0][idx] = z;
    }
}

// weights: gate remap + fp16 split
__global__ void prep_w_kernel(const float* __restrict__ whh1, const float* __restrict__ wih1,
                              const float* __restrict__ b1i,  const float* __restrict__ b1h,
                              const float* __restrict__ whh2, const float* __restrict__ wih2) {
    int idx = blockIdx.x * blockDim.x + threadIdx.x;
    if (idx >= Gn * Hn) return;
    int n = idx >> 8;                 // stored (remapped) row
    int k = idx & 255;
    int orig = ((n & 3) << 8) | (n >> 2);
    float v1 = whh1[orig * Hn + k];
    __half h1 = __float2half_rn(v1);
    g_w1hi[idx] = h1;
    g_w1lo[idx] = __float2half_rn(v1 - __half2float(h1));
    float v2 = whh2[orig * Hn + k];
    __half h2 = __float2half_rn(v2);
    g_w2hi[idx] = h2;
    g_w2lo[idx] = __float2half_rn(v2 - __half2float(h2));
    if (k < 16) {
        float x1 = (k < Fn) ? wih1[orig * Fn + k] : 0.f;
        __half xh1 = __float2half_rn(x1);
        g_wx1hi[n * 16 + k] = xh1;
        g_wx1lo[n * 16 + k] = __float2half_rn(x1 - __half2float(xh1));
        float x2 = (k < Fn) ? wih2[orig * 271 + k] : 0.f;
        __half xh2 = __float2half_rn(x2);
        g_wx2hi[n * 16 + k] = xh2;
        g_wx2lo[n * 16 + k] = __float2half_rn(x2 - __half2float(xh2));
    }
    if (k == 0) g_badd1[n] = b1i[orig] + b1h[orig];
}

// per-step inputs: xs[v][b][16] fp16 split (col 15 zero)
__global__ void prep_x_kernel(const float* __restrict__ state) {
    int idx = blockIdx.x * blockDim.x + threadIdx.x;
    if (idx >= Vn * Bsz * 16) return;
    int k = idx & 15;
    int b = (idx >> 4) & (Bsz - 1);
    int v = idx >> 16;                // Bsz*16 = 65536
    float val = (k < Fn) ? state[(size_t)b * (Vn * Fn) + v * Fn + k] : 0.f;
    __half h = __float2half_rn(val);
    g_xshi[idx] = h;
    g_xslo[idx] = __float2half_rn(val - __half2float(h));
}

// ---------------- fp32 gemm (MLP + pre2), proven in round 5 -----------------
template <int EPI, int REMAP, int W4>
__global__ void __launch_bounds__(256, 2) gemm3(
    const float* __restrict__ A,  int lda,
    const float* __restrict__ W,  int ldw, int K,
    const float* __restrict__ b1, const float* __restrict__ b2,
    float* __restrict__ C, int N)
{
    __shared__ float As[2][16][128];
    __shared__ float Bs[2][16][128];

    const int tid = threadIdx.x;
    const int tx = tid & 15;
    const int ty = tid >> 4;
    const int m0 = blockIdx.y * 128;
    const int n0 = blockIdx.x * 128;

    const int lr = tid >> 1;
    const int lc = (tid & 1) * 8;
    const int gn = n0 + lr;
    const int wrow = REMAP ? (((gn & 3) << 8) | (gn >> 2)) : gn;
    const float* Ap = A + (size_t)(m0 + lr) * lda + lc;
    const float* Wp = W + (size_t)wrow * ldw + lc;

    ull acc[8][4];
#pragma unroll
    for (int i = 0; i < 8; i++)
#pragma unroll
        for (int j = 0; j < 4; j++) acc[i][j] = 0ull;

    {
        float4 a0 = *(const float4*)Ap;
        float4 a1 = *(const float4*)(Ap + 4);
        float4 w0, w1;
        if (W4) { w0 = *(const float4*)Wp; w1 = *(const float4*)(Wp + 4); }
        else {
            w0 = make_float4(Wp[0], Wp[1], Wp[2], Wp[3]);
            w1 = make_float4(Wp[4], Wp[5], Wp[6], Wp[7]);
        }
        As[0][lc + 0][lr] = a0.x; As[0][lc + 1][lr] = a0.y;
        As[0][lc + 2][lr] = a0.z; As[0][lc + 3][lr] = a0.w;
        As[0][lc + 4][lr] = a1.x; As[0][lc + 5][lr] = a1.y;
        As[0][lc + 6][lr] = a1.z; As[0][lc + 7][lr] = a1.w;
        Bs[0][lc + 0][lr] = w0.x; Bs[0][lc + 1][lr] = w0.y;
        Bs[0][lc + 2][lr] = w0.z; Bs[0][lc + 3][lr] = w0.w;
        Bs[0][lc + 4][lr] = w1.x; Bs[0][lc + 5][lr] = w1.y;
        Bs[0][lc + 6][lr] = w1.z; Bs[0][lc + 7][lr] = w1.w;
    }
    __syncthreads();

    int cur = 0;
    for (int k0 = 0; k0 < K; k0 += 16) {
        const bool more = (k0 + 16) < K;
        float4 pa0, pa1, pw0, pw1;
        if (more) {
            pa0 = *(const float4*)(Ap + k0 + 16);
            pa1 = *(const float4*)(Ap + k0 + 20);
            const float* wq = Wp + k0 + 16;
            if (W4) { pw0 = *(const float4*)wq; pw1 = *(const float4*)(wq + 4); }
            else {
                pw0 = make_float4(wq[0], wq[1], wq[2], wq[3]);
                pw1 = make_float4(wq[4], wq[5], wq[6], wq[7]);
            }
        }
#pragma unroll
        for (int kk = 0; kk < 16; kk++) {
            float4 a0 = *(const float4*)&As[cur][kk][ty * 4];
            float4 a1 = *(const float4*)&As[cur][kk][64 + ty * 4];
            ulonglong2 bq0 = *(const ulonglong2*)&Bs[cur][kk][tx * 4];
            ulonglong2 bq1 = *(const ulonglong2*)&Bs[cur][kk][64 + tx * 4];
            float ar[8] = {a0.x, a0.y, a0.z, a0.w, a1.x, a1.y, a1.z, a1.w};
#pragma unroll
            for (int i = 0; i < 8; i++) {
                ull aa; dup2(aa, ar[i]);
                ffma2(acc[i][0], aa, bq0.x);
                ffma2(acc[i][1], aa, bq0.y);
                ffma2(acc[i][2], aa, bq1.x);
                ffma2(acc[i][3], aa, bq1.y);
            }
        }
        if (more) {
            int nx = cur ^ 1;
            As[nx][lc + 0][lr] = pa0.x; As[nx][lc + 1][lr] = pa0.y;
            As[nx][lc + 2][lr] = pa0.z; As[nx][lc + 3][lr] = pa0.w;
            As[nx][lc + 4][lr] = pa1.x; As[nx][lc + 5][lr] = pa1.y;
            As[nx][lc + 6][lr] = pa1.z; As[nx][lc + 7][lr] = pa1.w;
            Bs[nx][lc + 0][lr] = pw0.x; Bs[nx][lc + 1][lr] = pw0.y;
            Bs[nx][lc + 2][lr] = pw0.z; Bs[nx][lc + 3][lr] = pw0.w;
            Bs[nx][lc + 4][lr] = pw1.x; Bs[nx][lc + 5][lr] = pw1.y;
            Bs[nx][lc + 6][lr] = pw1.z; Bs[nx][lc + 7][lr] = pw1.w;
        }
        __syncthreads();
        cur ^= 1;
    }

    float add[8];
#pragma unroll
    for (int j = 0; j < 8; j++) {
        int n = n0 + ((j < 4) ? (4 * tx + j) : (64 + 4 * tx + (j - 4)));
        int rn = REMAP ? (((n & 3) << 8) | (n >> 2)) : n;
        float t = 0.f;
        if (b1) t += b1[rn];
        if (b2) t += b2[rn];
        add[j] = t;
    }
#pragma unroll
    for (int i = 0; i < 8; i++) {
        int m = m0 + ((i < 4) ? (4 * ty + i) : (64 + 4 * ty + (i - 4)));
        float o[8];
#pragma unroll
        for (int j4 = 0; j4 < 4; j4++) {
            float2 f = u2f(acc[i][j4]);
            o[2 * j4]     = f.x + add[2 * j4];
            o[2 * j4 + 1] = f.y + add[2 * j4 + 1];
        }
        if (EPI == 1) {
#pragma unroll
            for (int j = 0; j < 8; j++) o[j] = fmaxf(o[j], 0.f);
        }
        *(float4*)(C + (size_t)m * N + n0 + 4 * tx)      = make_float4(o[0], o[1], o[2], o[3]);
        *(float4*)(C + (size_t)m * N + n0 + 64 + 4 * tx) = make_float4(o[4], o[5], o[6], o[7]);
    }
}

// ---------------- pi head ---------------------------------------------------
__global__ void pi_kernel(const float* __restrict__ h2,
                          const float* __restrict__ piW,
                          const float* __restrict__ pib,
                          float* __restrict__ out, int v) {
    int gw = (blockIdx.x * blockDim.x + threadIdx.x) >> 5;
    int lane = threadIdx.x & 31;
    if (gw >= Bsz) return;
    const float* hr = h2 + (size_t)gw * Hn;
    float s = 0.f;
#pragma unroll
    for (int k = lane; k < Hn; k += 32) s += hr[k] * piW[k];
#pragma unroll
    for (int off = 16; off > 0; off >>= 1)
        s += __shfl_down_sync(0xffffffffu, s, off);
    if (lane == 0)
        out[(size_t)gw * Vn + v] = tanhf(s + pib[0]);
}

// ---------------- launch ----------------------------------------------------
extern "C" void kernel_launch(void* const* d_in, const int* in_sizes, int n_in,
                              void* d_out, int out_size) {
    const float* state  = (const float*)d_in[0];
    const float* l1_Wih = (const float*)d_in[1];
    const float* l1_Whh = (const float*)d_in[2];
    const float* l1_bih = (const float*)d_in[3];
    const float* l1_bhh = (const float*)d_in[4];
    const float* fc1_W  = (const float*)d_in[5];
    const float* fc1_b  = (const float*)d_in[6];
    const float* fc2_W  = (const float*)d_in[7];
    const float* fc2_b  = (const float*)d_in[8];
    const float* fc3_W  = (const float*)d_in[9];
    const float* fc3_b  = (const float*)d_in[10];
    const float* fc4_W  = (const float*)d_in[11];
    const float* fc4_b  = (const float*)d_in[12];
    const float* l2_Wih = (const float*)d_in[13];
    const float* l2_Whh = (const float*)d_in[14];
    const float* l2_bih = (const float*)d_in[15];
    const float* l2_bhh = (const float*)d_in[16];
    const float* pi_W   = (const float*)d_in[17];
    const float* pi_b   = (const float*)d_in[18];
    float* out = (float*)d_out;

    float *c1, *c2, *h1f, *h2f, *badd1, *m1, *m2, *m3, *m4, *pre2;
    __half *h1hi, *h1lo, *h2hi, *h2lo;
    __half *w1hi, *w1lo, *w2hi, *w2lo, *wx1hi, *wx1lo, *wx2hi, *wx2lo, *xshi, *xslo;
    cudaGetSymbolAddress((void**)&c1, g_c1);
    cudaGetSymbolAddress((void**)&c2, g_c2);
    cudaGetSymbolAddress((void**)&h1f, g_h1f);
    cudaGetSymbolAddress((void**)&h2f, g_h2f);
    cudaGetSymbolAddress((void**)&h1hi, g_h1hi);
    cudaGetSymbolAddress((void**)&h1lo, g_h1lo);
    cudaGetSymbolAddress((void**)&h2hi, g_h2hi);
    cudaGetSymbolAddress((void**)&h2lo, g_h2lo);
    cudaGetSymbolAddress((void**)&w1hi, g_w1hi);
    cudaGetSymbolAddress((void**)&w1lo, g_w1lo);
    cudaGetSymbolAddress((void**)&w2hi, g_w2hi);
    cudaGetSymbolAddress((void**)&w2lo, g_w2lo);
    cudaGetSymbolAddress((void**)&wx1hi, g_wx1hi);
    cudaGetSymbolAddress((void**)&wx1lo, g_wx1lo);
    cudaGetSymbolAddress((void**)&wx2hi, g_wx2hi);
    cudaGetSymbolAddress((void**)&wx2lo, g_wx2lo);
    cudaGetSymbolAddress((void**)&xshi, g_xshi);
    cudaGetSymbolAddress((void**)&xslo, g_xslo);
    cudaGetSymbolAddress((void**)&badd1, g_badd1);
    cudaGetSymbolAddress((void**)&m1, g_m1);
    cudaGetSymbolAddress((void**)&m2, g_m2);
    cudaGetSymbolAddress((void**)&m3, g_m3);
    cudaGetSymbolAddress((void**)&m4, g_m4);
    cudaGetSymbolAddress((void**)&pre2, g_pre2);

    const int HB = Bsz * Hn;   // ping-pong offset

    // ---- prep ----
    zero_states_kernel<<<(HB + 255) / 256, 256>>>();
    prep_w_kernel<<<(Gn * Hn + 255) / 256, 256>>>(l1_Whh, l1_Wih, l1_bih, l1_bhh, l2_Whh, l2_Wih);
    prep_x_kernel<<<(Vn * Bsz * 16 + 255) / 256, 256>>>(state);

    dim3 tgrid(Gn / 128, Bsz / 128);   // 8 x 32 = 256 CTAs

    // ---- LSTM1 scan (tensor-core fp16-split) ----
    for (int v = 0; v < Vn; v++) {
        int pi_ = v & 1, po = (v + 1) & 1;
        lstm_step_mma<0><<<tgrid, 256>>>(
            h1hi + pi_ * HB, h1lo + pi_ * HB,
            w1hi, w1lo, wx1hi, wx1lo,
            xshi + v * (Bsz * 16), xslo + v * (Bsz * 16),
            badd1, c1, h1f,
            h1hi + po * HB, h1lo + po * HB);
    }

    // ---- MLP stack (fp32 gemm) ----
    gemm3<1, 0, 1><<<dim3(1024 / 128, 32), 256>>>(h1f, Hn, fc1_W, Hn, Hn, fc1_b, nullptr, m1, 1024);
    gemm3<1, 0, 1><<<dim3(1024 / 128, 32), 256>>>(m1, 1024, fc2_W, 1024, 1024, fc2_b, nullptr, m2, 1024);
    gemm3<1, 0, 1><<<dim3(512 / 128, 32), 256>>>(m2, 1024, fc3_W, 1024, 1024, fc3_b, nullptr, m3, 512);
    gemm3<1, 0, 1><<<dim3(256 / 128, 32), 256>>>(m3, 512, fc4_W, 512, 512, fc4_b, nullptr, m4, 256);

    // ---- pre2 = m4 @ Wih2[:,15:].T + bih + bhh (remapped col order) ----
    gemm3<0, 1, 0><<<dim3(Gn / 128, 32), 256>>>(m4, 256, l2_Wih + 15, 271, 256, l2_bih, l2_bhh, pre2, Gn);

    // ---- LSTM2 scan + pi head ----
    for (int v = 0; v < Vn; v++) {
        int pi_ = v & 1, po = (v + 1) & 1;
        lstm_step_mma<1><<<tgrid, 256>>>(
            h2hi + pi_ * HB, h2lo + pi_ * HB,
            w2hi, w2lo, wx2hi, wx2lo,
            xshi + v * (Bsz * 16), xslo + v * (Bsz * 16),
            pre2, c2, h2f,
            h2hi + po * HB, h2lo + po * HB);
        pi_kernel<<<Bsz / 8, 256>>>(h2f, pi_W, pi_b, out, v);
    }
}

// round 10
// speedup vs baseline: 1.0436x; 1.0436x over previous
#include <cuda_runtime.h>
#include <cuda_fp16.h>
#include <cstdint>

// Problem constants
#define Bsz 4096
#define Vn  50
#define Fn  15
#define Hn  256
#define Gn  1024   // 4*H

// ---------------- scratch (static device globals; no allocation) ----------
__device__ float g_c1 [Bsz * Hn];
__device__ float g_c2 [Bsz * Hn];
__device__ float g_h1f[Bsz * Hn];
__device__ float g_h2f[Bsz * Hn];
// ping-pong fp16-split hidden states (race-free across a scan step)
__device__ __half g_h1hi[2][Bsz * Hn];
__device__ __half g_h1lo[2][Bsz * Hn];
__device__ __half g_h2hi[2][Bsz * Hn];
__device__ __half g_h2lo[2][Bsz * Hn];
// fp16-split, gate-remapped weights  [n'][256] with n' = 4u+gate interleave
__device__ __half g_w1hi[Gn * Hn], g_w1lo[Gn * Hn];
__device__ __half g_w2hi[Gn * Hn], g_w2lo[Gn * Hn];
__device__ __half g_wx1hi[Gn * 16], g_wx1lo[Gn * 16];
__device__ __half g_wx2hi[Gn * 16], g_wx2lo[Gn * 16];
// fp16-split per-step inputs xs[v][b][16] (col 15 zero)
__device__ __half g_xshi[Vn * Bsz * 16], g_xslo[Vn * Bsz * 16];
__device__ float g_badd1[Gn];           // lstm1 bih+bhh, remapped order
__device__ float g_m1[Bsz * 1024];
__device__ float g_m2[Bsz * 1024];
__device__ float g_m3[Bsz * 512];
__device__ float g_m4[Bsz * 256];
__device__ float g_pre2[Bsz * Gn];

typedef unsigned long long ull;

__device__ __forceinline__ void dup2(ull& d, float s) {
    asm("mov.b64 %0,{%1,%1};" : "=l"(d) : "f"(s));
}
__device__ __forceinline__ void ffma2(ull& d, ull a, ull b) {
    asm("fma.rn.f32x2 %0,%1,%2,%0;" : "+l"(d) : "l"(a), "l"(b));
}
__device__ __forceinline__ float2 u2f(ull u) {
    float2 f; asm("mov.b64 {%0,%1},%2;" : "=f"(f.x), "=f"(f.y) : "l"(u)); return f;
}
__device__ __forceinline__ float fsig(float x)  { return 1.0f / (1.0f + expf(-x)); }

// ---------------- warp-MMA helpers (sm_80+ baseline; runs as HMMA) ----------
__device__ __forceinline__ uint32_t smem_u32(const void* p) {
    uint32_t a;
    asm("{ .reg .u64 t; cvta.to.shared.u64 t, %1; cvt.u32.u64 %0, t; }" : "=r"(a) : "l"(p));
    return a;
}
__device__ __forceinline__ void ldm_x4(uint32_t* r, uint32_t addr) {
    asm volatile("ldmatrix.sync.aligned.m8n8.x4.shared.b16 {%0,%1,%2,%3}, [%4];"
        : "=r"(r[0]), "=r"(r[1]), "=r"(r[2]), "=r"(r[3]) : "r"(addr));
}
__device__ __forceinline__ void ldm_x2(uint32_t* r, uint32_t addr) {
    asm volatile("ldmatrix.sync.aligned.m8n8.x2.shared.b16 {%0,%1}, [%2];"
        : "=r"(r[0]), "=r"(r[1]) : "r"(addr));
}
__device__ __forceinline__ void mma16816(float* d, const uint32_t* a, const uint32_t* b) {
    asm volatile("mma.sync.aligned.m16n8k16.row.col.f32.f16.f16.f32 "
        "{%0,%1,%2,%3},{%4,%5,%6,%7},{%8,%9},{%0,%1,%2,%3};"
        : "+f"(d[0]), "+f"(d[1]), "+f"(d[2]), "+f"(d[3])
        : "r"(a[0]), "r"(a[1]), "r"(a[2]), "r"(a[3]), "r"(b[0]), "r"(b[1]));
}
__device__ __forceinline__ void cp16(uint32_t d, const void* s) {
    asm volatile("cp.async.cg.shared.global [%0], [%1], 16;" :: "r"(d), "l"(s));
}
#define CP_COMMIT() asm volatile("cp.async.commit_group;" ::: "memory")
#define CP_WAIT0()  asm volatile("cp.async.wait_group 0;" ::: "memory")

// smem row stride (halves): 16 data + 8 pad = 48 B/row. 16B-aligned; row start
// banks 12r mod 32 tile all 32 banks across 8 rows -> conflict-free ldmatrix.
#define LDP 24

// ---------------- fused LSTM step (fp16-split MMA, cp.async pipeline) -------
// CTA tile 64m x 128n, 8 warps (2m x 4n), warp tile 32x32 -> acc 32 regs,
// 3 CTAs/SM (24 warps) for latency hiding. gates = h@Whh'^T + x@Wx'^T via
// 3 passes (hi*hi + hi*lo + lo*hi) of m16n8k16 f16 MMA, fp32 accumulate.
template <int USE_PRE2>
__global__ void __launch_bounds__(256, 3) lstm_step_mma(
    const __half* __restrict__ hA_hi, const __half* __restrict__ hA_lo,
    const __half* __restrict__ W_hi,  const __half* __restrict__ W_lo,
    const __half* __restrict__ Wx_hi, const __half* __restrict__ Wx_lo,
    const __half* __restrict__ xs_hi, const __half* __restrict__ xs_lo,
    const float* __restrict__ preact,
    float* __restrict__ cSt, float* __restrict__ hF,
    __half* __restrict__ hO_hi, __half* __restrict__ hO_lo)
{
    __shared__ __align__(16) __half shA[2][2][64 * LDP];    // [buf][hi/lo]
    __shared__ __align__(16) __half shW[2][2][128 * LDP];

    const int tid  = threadIdx.x;
    const int wid  = tid >> 5;
    const int lane = tid & 31;
    const int n0 = blockIdx.x * 128;   // remapped gate-col base
    const int m0 = blockIdx.y * 64;    // batch-row base
    const int wm0 = (wid & 1) * 32;    // warp m offset
    const int wn0 = (wid >> 1) * 32;   // warp n offset

    float acc[2][4][4];
#pragma unroll
    for (int i = 0; i < 2; i++)
#pragma unroll
        for (int j = 0; j < 4; j++)
#pragma unroll
            for (int k = 0; k < 4; k++) acc[i][j][k] = 0.f;

    // cp.async staging: 768 16B-granules (A:256, W:512), 3 per thread,
    // all sharing (hl, blk) so each thread uses one hi-or-lo source set.
    const int arow = tid >> 2;          // 0..63
    const int ahl  = (tid >> 1) & 1;    // hi(0)/lo(1)
    const int ablk = tid & 1;           // 8-half block within 16
    const uint32_t dOff = (uint32_t)(arow * LDP + ablk * 8) * 2;  // bytes

    const __half* baseA  = (ahl ? hA_lo : hA_hi) + (size_t)(m0 + arow) * Hn + ablk * 8;
    const __half* baseW1 = (ahl ? W_lo  : W_hi)  + (size_t)(n0 + arow) * Hn + ablk * 8;
    const __half* baseW2 = (ahl ? W_lo  : W_hi)  + (size_t)(n0 + arow + 64) * Hn + ablk * 8;
    const __half* baseAx  = (ahl ? xs_lo  : xs_hi)  + (size_t)(m0 + arow) * 16 + ablk * 8;
    const __half* baseWx1 = (ahl ? Wx_lo : Wx_hi) + (size_t)(n0 + arow) * 16 + ablk * 8;
    const __half* baseWx2 = (ahl ? Wx_lo : Wx_hi) + (size_t)(n0 + arow + 64) * 16 + ablk * 8;

    const uint32_t sAh[2] = { smem_u32(&shA[0][0][0]), smem_u32(&shA[1][0][0]) };
    const uint32_t sAl[2] = { smem_u32(&shA[0][1][0]), smem_u32(&shA[1][1][0]) };
    const uint32_t sWh[2] = { smem_u32(&shW[0][0][0]), smem_u32(&shW[1][0][0]) };
    const uint32_t sWl[2] = { smem_u32(&shW[0][1][0]), smem_u32(&shW[1][1][0]) };
    const uint32_t dA = (ahl ? sAl[0] : sAh[0]) - sAh[0];   // 0 or region delta? (same array)
    // direct per-(buf) destination addresses:
    //   A  : (ahl? sAl : sAh)[buf] + dOff
    //   W1 : (ahl? sWl : sWh)[buf] + dOff
    //   W2 : (ahl? sWl : sWh)[buf] + dOff + 64*LDP*2
    (void)dA;

    auto stage = [&](int buf, int c) {
        const __half *pA, *pW1, *pW2;
        if (c < 16) {
            pA  = baseA  + c * 16;
            pW1 = baseW1 + c * 16;
            pW2 = baseW2 + c * 16;
        } else {
            pA = baseAx; pW1 = baseWx1; pW2 = baseWx2;
        }
        uint32_t da = (ahl ? sAl[buf] : sAh[buf]) + dOff;
        uint32_t dw = (ahl ? sWl[buf] : sWh[buf]) + dOff;
        cp16(da, pA);
        cp16(dw, pW1);
        cp16(dw + 64 * LDP * 2, pW2);
    };

    // ldmatrix lane addressing
    const int l15 = lane & 15;
    const uint32_t aoff = ((uint32_t)((wm0 + l15) * LDP + (lane >> 4) * 8)) * 2;
    const int bl = lane & 7;
    const uint32_t boffbase = ((uint32_t)((wn0 + bl) * LDP + ((lane >> 3) & 1) * 8)) * 2;

    // ---- preload chunk 0 ----
    stage(0, 0);
    CP_COMMIT();
    CP_WAIT0();
    __syncthreads();

    for (int c = 0; c < 17; c++) {
        if (c < 16) {
            stage((c + 1) & 1, c + 1);
            CP_COMMIT();
        }
        const int cb = c & 1;
        // ---- B fragments for this k16 (4 n-frags, hi+lo) ----
        uint32_t bh[4][2], blo[4][2];
#pragma unroll
        for (int nf = 0; nf < 4; nf++) {
            uint32_t bo = boffbase + (uint32_t)(nf * 8 * LDP) * 2;
            ldm_x2(bh[nf], sWh[cb] + bo);
            ldm_x2(blo[nf], sWl[cb] + bo);
        }
        // ---- A fragments per m-tile, 3-pass MMA ----
#pragma unroll
        for (int mt = 0; mt < 2; mt++) {
            uint32_t ao = aoff + (uint32_t)(mt * 16 * LDP) * 2;
            uint32_t ah[4], al[4];
            ldm_x4(ah, sAh[cb] + ao);
            ldm_x4(al, sAl[cb] + ao);
#pragma unroll
            for (int nf = 0; nf < 4; nf++) {
                mma16816(acc[mt][nf], ah, bh[nf]);
                mma16816(acc[mt][nf], ah, blo[nf]);
                mma16816(acc[mt][nf], al, bh[nf]);
            }
        }
        if (c < 16) {
            CP_WAIT0();
            __syncthreads();
        }
    }

    // ---- epilogue: combine gate pairs via shfl, LSTM cell update ----
    const bool odd = (lane & 1);
#pragma unroll
    for (int mt = 0; mt < 2; mt++) {
#pragma unroll
        for (int nf = 0; nf < 4; nf++) {
            float c0 = acc[mt][nf][0], c1 = acc[mt][nf][1];
            float c2 = acc[mt][nf][2], c3 = acc[mt][nf][3];
            // even lanes hold (i,f) of rows r,r+8; odd lanes hold (g,o)
            float v0 = odd ? c0 : c2;
            float v1 = odd ? c1 : c3;
            float r0 = __shfl_xor_sync(0xffffffffu, v0, 1);
            float r1 = __shfl_xor_sync(0xffffffffu, v1, 1);
            float gi = odd ? r0 : c0;
            float gf = odd ? r1 : c1;
            float gg = odd ? c2 : r0;
            float go = odd ? c3 : r1;
            int m = m0 + wm0 + mt * 16 + (lane >> 2) + (odd ? 8 : 0);
            int nb = n0 + wn0 + nf * 8 + ((lane >> 1) & 1) * 4;   // = 4*u
            float4 p = USE_PRE2 ? *(const float4*)(preact + (size_t)m * Gn + nb)
                                : *(const float4*)(preact + nb);
            gi += p.x; gf += p.y; gg += p.z; go += p.w;
            int u = nb >> 2;
            size_t ci = (size_t)m * Hn + u;
            float cold = cSt[ci];
            float iv = fsig(gi), fv = fsig(gf);
            float gv = tanhf(gg), ov = fsig(go);
            float cn = fv * cold + iv * gv;
            cSt[ci] = cn;
            float h = ov * tanhf(cn);
            hF[ci] = h;
            __half hh = __float2half_rn(h);
            hO_hi[ci] = hh;
            hO_lo[ci] = __float2half_rn(h - __half2float(hh));
        }
    }
}

// ---------------- prep kernels ----------------------------------------------
__global__ void zero_states_kernel() {
    int idx = blockIdx.x * blockDim.x + threadIdx.x;
    if (idx < Bsz * Hn) {
        g_c1[idx] = 0.f; g_c2[idx] = 0.f;
        __half z = __float2half_rn(0.f);
        g_h1hi[0][idx] = z; g_h1lo[0][idx] = z;
        g_h2hi[0][idx] = z; g_h2lo[0][idx] = z;
    }
}

// weights: gate remap + fp16 split
__global__ void prep_w_kernel(const float* __restrict__ whh1, const float* __restrict__ wih1,
                              const float* __restrict__ b1i,  const float* __restrict__ b1h,
                              const float* __restrict__ whh2, const float* __restrict__ wih2) {
    int idx = blockIdx.x * blockDim.x + threadIdx.x;
    if (idx >= Gn * Hn) return;
    int n = idx >> 8;                 // stored (remapped) row
    int k = idx & 255;
    int orig = ((n & 3) << 8) | (n >> 2);
    float v1 = whh1[orig * Hn + k];
    __half h1 = __float2half_rn(v1);
    g_w1hi[idx] = h1;
    g_w1lo[idx] = __float2half_rn(v1 - __half2float(h1));
    float v2 = whh2[orig * Hn + k];
    __half h2 = __float2half_rn(v2);
    g_w2hi[idx] = h2;
    g_w2lo[idx] = __float2half_rn(v2 - __half2float(h2));
    if (k < 16) {
        float x1 = (k < Fn) ? wih1[orig * Fn + k] : 0.f;
        __half xh1 = __float2half_rn(x1);
        g_wx1hi[n * 16 + k] = xh1;
        g_wx1lo[n * 16 + k] = __float2half_rn(x1 - __half2float(xh1));
        float x2 = (k < Fn) ? wih2[orig * 271 + k] : 0.f;
        __half xh2 = __float2half_rn(x2);
        g_wx2hi[n * 16 + k] = xh2;
        g_wx2lo[n * 16 + k] = __float2half_rn(x2 - __half2float(xh2));
    }
    if (k == 0) g_badd1[n] = b1i[orig] + b1h[orig];
}

// per-step inputs: xs[v][b][16] fp16 split (col 15 zero)
__global__ void prep_x_kernel(const float* __restrict__ state) {
    int idx = blockIdx.x * blockDim.x + threadIdx.x;
    if (idx >= Vn * Bsz * 16) return;
    int k = idx & 15;
    int b = (idx >> 4) & (Bsz - 1);
    int v = idx >> 16;                // Bsz*16 = 65536
    float val = (k < Fn) ? state[(size_t)b * (Vn * Fn) + v * Fn + k] : 0.f;
    __half h = __float2half_rn(val);
    g_xshi[idx] = h;
    g_xslo[idx] = __float2half_rn(val - __half2float(h));
}

// ---------------- fp32 gemm (MLP + pre2), proven in round 5 -----------------
template <int EPI, int REMAP, int W4>
__global__ void __launch_bounds__(256, 2) gemm3(
    const float* __restrict__ A,  int lda,
    const float* __restrict__ W,  int ldw, int K,
    const float* __restrict__ b1, const float* __restrict__ b2,
    float* __restrict__ C, int N)
{
    __shared__ float As[2][16][128];
    __shared__ float Bs[2][16][128];

    const int tid = threadIdx.x;
    const int tx = tid & 15;
    const int ty = tid >> 4;
    const int m0 = blockIdx.y * 128;
    const int n0 = blockIdx.x * 128;

    const int lr = tid >> 1;
    const int lc = (tid & 1) * 8;
    const int gn = n0 + lr;
    const int wrow = REMAP ? (((gn & 3) << 8) | (gn >> 2)) : gn;
    const float* Ap = A + (size_t)(m0 + lr) * lda + lc;
    const float* Wp = W + (size_t)wrow * ldw + lc;

    ull acc[8][4];
#pragma unroll
    for (int i = 0; i < 8; i++)
#pragma unroll
        for (int j = 0; j < 4; j++) acc[i][j] = 0ull;

    {
        float4 a0 = *(const float4*)Ap;
        float4 a1 = *(const float4*)(Ap + 4);
        float4 w0, w1;
        if (W4) { w0 = *(const float4*)Wp; w1 = *(const float4*)(Wp + 4); }
        else {
            w0 = make_float4(Wp[0], Wp[1], Wp[2], Wp[3]);
            w1 = make_float4(Wp[4], Wp[5], Wp[6], Wp[7]);
        }
        As[0][lc + 0][lr] = a0.x; As[0][lc + 1][lr] = a0.y;
        As[0][lc + 2][lr] = a0.z; As[0][lc + 3][lr] = a0.w;
        As[0][lc + 4][lr] = a1.x; As[0][lc + 5][lr] = a1.y;
        As[0][lc + 6][lr] = a1.z; As[0][lc + 7][lr] = a1.w;
        Bs[0][lc + 0][lr] = w0.x; Bs[0][lc + 1][lr] = w0.y;
        Bs[0][lc + 2][lr] = w0.z; Bs[0][lc + 3][lr] = w0.w;
        Bs[0][lc + 4][lr] = w1.x; Bs[0][lc + 5][lr] = w1.y;
        Bs[0][lc + 6][lr] = w1.z; Bs[0][lc + 7][lr] = w1.w;
    }
    __syncthreads();

    int cur = 0;
    for (int k0 = 0; k0 < K; k0 += 16) {
        const bool more = (k0 + 16) < K;
        float4 pa0, pa1, pw0, pw1;
        if (more) {
            pa0 = *(const float4*)(Ap + k0 + 16);
            pa1 = *(const float4*)(Ap + k0 + 20);
            const float* wq = Wp + k0 + 16;
            if (W4) { pw0 = *(const float4*)wq; pw1 = *(const float4*)(wq + 4); }
            else {
                pw0 = make_float4(wq[0], wq[1], wq[2], wq[3]);
                pw1 = make_float4(wq[4], wq[5], wq[6], wq[7]);
            }
        }
#pragma unroll
        for (int kk = 0; kk < 16; kk++) {
            float4 a0 = *(const float4*)&As[cur][kk][ty * 4];
            float4 a1 = *(const float4*)&As[cur][kk][64 + ty * 4];
            ulonglong2 bq0 = *(const ulonglong2*)&Bs[cur][kk][tx * 4];
            ulonglong2 bq1 = *(const ulonglong2*)&Bs[cur][kk][64 + tx * 4];
            float ar[8] = {a0.x, a0.y, a0.z, a0.w, a1.x, a1.y, a1.z, a1.w};
#pragma unroll
            for (int i = 0; i < 8; i++) {
                ull aa; dup2(aa, ar[i]);
                ffma2(acc[i][0], aa, bq0.x);
                ffma2(acc[i][1], aa, bq0.y);
                ffma2(acc[i][2], aa, bq1.x);
                ffma2(acc[i][3], aa, bq1.y);
            }
        }
        if (more) {
            int nx = cur ^ 1;
            As[nx][lc + 0][lr] = pa0.x; As[nx][lc + 1][lr] = pa0.y;
            As[nx][lc + 2][lr] = pa0.z; As[nx][lc + 3][lr] = pa0.w;
            As[nx][lc + 4][lr] = pa1.x; As[nx][lc + 5][lr] = pa1.y;
            As[nx][lc + 6][lr] = pa1.z; As[nx][lc + 7][lr] = pa1.w;
            Bs[nx][lc + 0][lr] = pw0.x; Bs[nx][lc + 1][lr] = pw0.y;
            Bs[nx][lc + 2][lr] = pw0.z; Bs[nx][lc + 3][lr] = pw0.w;
            Bs[nx][lc + 4][lr] = pw1.x; Bs[nx][lc + 5][lr] = pw1.y;
            Bs[nx][lc + 6][lr] = pw1.z; Bs[nx][lc + 7][lr] = pw1.w;
        }
        __syncthreads();
        cur ^= 1;
    }

    float add[8];
#pragma unroll
    for (int j = 0; j < 8; j++) {
        int n = n0 + ((j < 4) ? (4 * tx + j) : (64 + 4 * tx + (j - 4)));
        int rn = REMAP ? (((n & 3) << 8) | (n >> 2)) : n;
        float t = 0.f;
        if (b1) t += b1[rn];
        if (b2) t += b2[rn];
        add[j] = t;
    }
#pragma unroll
    for (int i = 0; i < 8; i++) {
        int m = m0 + ((i < 4) ? (4 * ty + i) : (64 + 4 * ty + (i - 4)));
        float o[8];
#pragma unroll
        for (int j4 = 0; j4 < 4; j4++) {
            float2 f = u2f(acc[i][j4]);
            o[2 * j4]     = f.x + add[2 * j4];
            o[2 * j4 + 1] = f.y + add[2 * j4 + 1];
        }
        if (EPI == 1) {
#pragma unroll
            for (int j = 0; j < 8; j++) o[j] = fmaxf(o[j], 0.f);
        }
        *(float4*)(C + (size_t)m * N + n0 + 4 * tx)      = make_float4(o[0], o[1], o[2], o[3]);
        *(float4*)(C + (size_t)m * N + n0 + 64 + 4 * tx) = make_float4(o[4], o[5], o[6], o[7]);
    }
}

// ---------------- pi head ---------------------------------------------------
__global__ void pi_kernel(const float* __restrict__ h2,
                          const float* __restrict__ piW,
                          const float* __restrict__ pib,
                          float* __restrict__ out, int v) {
    int gw = (blockIdx.x * blockDim.x + threadIdx.x) >> 5;
    int lane = threadIdx.x & 31;
    if (gw >= Bsz) return;
    const float* hr = h2 + (size_t)gw * Hn;
    float s = 0.f;
#pragma unroll
    for (int k = lane; k < Hn; k += 32) s += hr[k] * piW[k];
#pragma unroll
    for (int off = 16; off > 0; off >>= 1)
        s += __shfl_down_sync(0xffffffffu, s, off);
    if (lane == 0)
        out[(size_t)gw * Vn + v] = tanhf(s + pib[0]);
}

// ---------------- launch ----------------------------------------------------
extern "C" void kernel_launch(void* const* d_in, const int* in_sizes, int n_in,
                              void* d_out, int out_size) {
    const float* state  = (const float*)d_in[0];
    const float* l1_Wih = (const float*)d_in[1];
    const float* l1_Whh = (const float*)d_in[2];
    const float* l1_bih = (const float*)d_in[3];
    const float* l1_bhh = (const float*)d_in[4];
    const float* fc1_W  = (const float*)d_in[5];
    const float* fc1_b  = (const float*)d_in[6];
    const float* fc2_W  = (const float*)d_in[7];
    const float* fc2_b  = (const float*)d_in[8];
    const float* fc3_W  = (const float*)d_in[9];
    const float* fc3_b  = (const float*)d_in[10];
    const float* fc4_W  = (const float*)d_in[11];
    const float* fc4_b  = (const float*)d_in[12];
    const float* l2_Wih = (const float*)d_in[13];
    const float* l2_Whh = (const float*)d_in[14];
    const float* l2_bih = (const float*)d_in[15];
    const float* l2_bhh = (const float*)d_in[16];
    const float* pi_W   = (const float*)d_in[17];
    const float* pi_b   = (const float*)d_in[18];
    float* out = (float*)d_out;

    float *c1, *c2, *h1f, *h2f, *badd1, *m1, *m2, *m3, *m4, *pre2;
    __half *h1hi, *h1lo, *h2hi, *h2lo;
    __half *w1hi, *w1lo, *w2hi, *w2lo, *wx1hi, *wx1lo, *wx2hi, *wx2lo, *xshi, *xslo;
    cudaGetSymbolAddress((void**)&c1, g_c1);
    cudaGetSymbolAddress((void**)&c2, g_c2);
    cudaGetSymbolAddress((void**)&h1f, g_h1f);
    cudaGetSymbolAddress((void**)&h2f, g_h2f);
    cudaGetSymbolAddress((void**)&h1hi, g_h1hi);
    cudaGetSymbolAddress((void**)&h1lo, g_h1lo);
    cudaGetSymbolAddress((void**)&h2hi, g_h2hi);
    cudaGetSymbolAddress((void**)&h2lo, g_h2lo);
    cudaGetSymbolAddress((void**)&w1hi, g_w1hi);
    cudaGetSymbolAddress((void**)&w1lo, g_w1lo);
    cudaGetSymbolAddress((void**)&w2hi, g_w2hi);
    cudaGetSymbolAddress((void**)&w2lo, g_w2lo);
    cudaGetSymbolAddress((void**)&wx1hi, g_wx1hi);
    cudaGetSymbolAddress((void**)&wx1lo, g_wx1lo);
    cudaGetSymbolAddress((void**)&wx2hi, g_wx2hi);
    cudaGetSymbolAddress((void**)&wx2lo, g_wx2lo);
    cudaGetSymbolAddress((void**)&xshi, g_xshi);
    cudaGetSymbolAddress((void**)&xslo, g_xslo);
    cudaGetSymbolAddress((void**)&badd1, g_badd1);
    cudaGetSymbolAddress((void**)&m1, g_m1);
    cudaGetSymbolAddress((void**)&m2, g_m2);
    cudaGetSymbolAddress((void**)&m3, g_m3);
    cudaGetSymbolAddress((void**)&m4, g_m4);
    cudaGetSymbolAddress((void**)&pre2, g_pre2);

    const int HB = Bsz * Hn;   // ping-pong offset

    // ---- prep ----
    zero_states_kernel<<<(HB + 255) / 256, 256>>>();
    prep_w_kernel<<<(Gn * Hn + 255) / 256, 256>>>(l1_Whh, l1_Wih, l1_bih, l1_bhh, l2_Whh, l2_Wih);
    prep_x_kernel<<<(Vn * Bsz * 16 + 255) / 256, 256>>>(state);

    dim3 tgrid(Gn / 128, Bsz / 64);   // 8 x 64 = 512 CTAs

    // ---- LSTM1 scan (tensor-core fp16-split) ----
    for (int v = 0; v < Vn; v++) {
        int pi_ = v & 1, po = (v + 1) & 1;
        lstm_step_mma<0><<<tgrid, 256>>>(
            h1hi + pi_ * HB, h1lo + pi_ * HB,
            w1hi, w1lo, wx1hi, wx1lo,
            xshi + v * (Bsz * 16), xslo + v * (Bsz * 16),
            badd1, c1, h1f,
            h1hi + po * HB, h1lo + po * HB);
    }

    // ---- MLP stack (fp32 gemm) ----
    gemm3<1, 0, 1><<<dim3(1024 / 128, 32), 256>>>(h1f, Hn, fc1_W, Hn, Hn, fc1_b, nullptr, m1, 1024);
    gemm3<1, 0, 1><<<dim3(1024 / 128, 32), 256>>>(m1, 1024, fc2_W, 1024, 1024, fc2_b, nullptr, m2, 1024);
    gemm3<1, 0, 1><<<dim3(512 / 128, 32), 256>>>(m2, 1024, fc3_W, 1024, 1024, fc3_b, nullptr, m3, 512);
    gemm3<1, 0, 1><<<dim3(256 / 128, 32), 256>>>(m3, 512, fc4_W, 512, 512, fc4_b, nullptr, m4, 256);

    // ---- pre2 = m4 @ Wih2[:,15:].T + bih + bhh (remapped col order) ----
    gemm3<0, 1, 0><<<dim3(Gn / 128, 32), 256>>>(m4, 256, l2_Wih + 15, 271, 256, l2_bih, l2_bhh, pre2, Gn);

    // ---- LSTM2 scan + pi head ----
    for (int v = 0; v < Vn; v++) {
        int pi_ = v & 1, po = (v + 1) & 1;
        lstm_step_mma<1><<<tgrid, 256>>>(
            h2hi + pi_ * HB, h2lo + pi_ * HB,
            w2hi, w2lo, wx2hi, wx2lo,
            xshi + v * (Bsz * 16), xslo + v * (Bsz * 16),
            pre2, c2, h2f,
            h2hi + po * HB, h2lo + po * HB);
        pi_kernel<<<Bsz / 8, 256>>>(h2f, pi_W, pi_b, out, v);
    }
}